// round 16
// baseline (speedup 1.0000x reference)
#include <cuda_runtime.h>
#include <cuda_bf16.h>
#include <math.h>

#define BB 8
#define SEQ 4096
#define DM 1024
#define NS 64
#define SCH 64          // scan steps per smem chunk
#define CHUNK 512       // sequence chunk per CTA (parallel-in-time)
#define WARM 64         // warmup steps (state error <= 0.7311^64 ~ 2e-9)
#define NCHUNK (SEQ / CHUNK)

typedef unsigned long long u64;
typedef unsigned int u32;

// ---------------- static scratch (no allocations allowed) ----------------
__device__ __align__(16) float g_Bs[NS * DM];              // sigmoid(B_w), [N, D]
__device__ __align__(16) float g_Aperm[DM * NS];           // sigmoid(A_raw), permuted n
__device__ __align__(16) float g_Cperm[DM * NS];           // sigmoid(C_w), permuted n
__device__ __align__(16) float g_g[DM];                    // sigmoid(gamma)
__device__ __align__(16) float g_sumC[DM];                 // sum_n sigmoid(C_w[d,n])
__device__ __align__(16) float g_U[(size_t)BB * SEQ * NS]; // X @ Bm^T, permuted n
__device__ __align__(16) float g_umin[(size_t)BB * SEQ];   // min_n U[b,s,n]
__device__ __align__(16) __nv_bfloat16 g_Ybf[(size_t)BB * SEQ * DM]; // y pre-norm, bf16

__device__ __forceinline__ float sigmoidf_(float v) {
    return 1.0f / (1.0f + expf(-v));
}

// ---------------- packed f32x2 helpers ----------------
__device__ __forceinline__ u64 pack2(float lo, float hi) {
    u64 r;
    asm("mov.b64 %0, {%1, %2};" : "=l"(r) : "f"(lo), "f"(hi));
    return r;
}
__device__ __forceinline__ void unpack2(u64 v, float& lo, float& hi) {
    asm("mov.b64 {%0, %1}, %2;" : "=f"(lo), "=f"(hi) : "l"(v));
}
__device__ __forceinline__ u64 fma2_(u64 a, u64 b, u64 c) {
    u64 r;
    asm("fma.rn.f32x2 %0, %1, %2, %3;" : "=l"(r) : "l"(a), "l"(b), "l"(c));
    return r;
}

// State update, one pair: h = min(1, h*A + u*x). Lower clip provably dead
// (u>=0, x>=0, A>0, h0=0 => h*A+u*x >= 0). min on ALU pipe.
__device__ __forceinline__ void step_pair(float& h0, float& h1, u64 u2, u64 xp, u64 a2) {
    asm("{\n\t"
        ".reg .b64 t, hp;\n\t"
        "mul.rn.f32x2 t, %2, %3;\n\t"
        "mov.b64 hp, {%0, %1};\n\t"
        "fma.rn.f32x2 hp, hp, %4, t;\n\t"
        "mov.b64 {%0, %1}, hp;\n\t"
        "}\n\t"
        : "+f"(h0), "+f"(h1) : "l"(u2), "l"(xp), "l"(a2));
    h0 = fminf(h0, 1.0f);
    h1 = fminf(h1, 1.0f);
}

__device__ __forceinline__ void dot_pair(u64& p2, float h0, float h1, u64 c2) {
    asm("{\n\t"
        ".reg .b64 hp;\n\t"
        "mov.b64 hp, {%1, %2};\n\t"
        "fma.rn.f32x2 %0, hp, %3, %0;\n\t"
        "}\n\t"
        : "+l"(p2) : "f"(h0), "f"(h1), "l"(c2));
}

// permutation: state n -> storage position, lane lp=n%4 owns n = lp + 4j,
// stored at lp*16 + j so each lane reads 16 contiguous floats (4x LDG.128)
__device__ __forceinline__ int permn(int n) { return ((n & 3) << 4) | (n >> 2); }

// ---------------- kernel 1: precompute sigmoids ----------------
__global__ void prep_kernel(const float* __restrict__ A_raw,
                            const float* __restrict__ B_w,
                            const float* __restrict__ C_w,
                            const float* __restrict__ gamma) {
    int i = blockIdx.x * 256 + threadIdx.x;
    if (i < NS * DM) {
        g_Bs[i] = sigmoidf_(B_w[i]);           // B_w is [N, D]
        int d = i >> 6, n = i & 63;            // A_raw / C_w are [D, N]
        int p = permn(n);
        g_Aperm[(d << 6) + p] = sigmoidf_(A_raw[i]);
        g_Cperm[(d << 6) + p] = sigmoidf_(C_w[i]);
    }
    if (i < DM) {
        g_g[i] = sigmoidf_(gamma[i]);
        float s = 0.0f;
        for (int n = 0; n < NS; n++) s += sigmoidf_(C_w[i * NS + n]);
        g_sumC[i] = s;    // y_d when all 64 states saturate at 1.0
    }
}

// ---------------- kernel 2: U = X @ Bs^T, k-paired f32x2 + fused umin ----
// 64 rows x 64 cols per block, 128 threads, thread = 4 rows x 8 cols.
// Both operands are NATURAL k-pairs (no dup, no packs): acc lane-lo holds
// even-k partial sum, lane-hi odd-k; added in the epilogue. Smem traffic
// = 1.5 B/MAC (vs 2.0 before). umin fused: row min over the 8 tx lanes.
__global__ void __launch_bounds__(128) gemm_kernel(const float* __restrict__ X) {
    __shared__ __align__(16) u64 Xs[2][16][66];  // [buf][kpair][row], pad 2
    __shared__ __align__(16) u64 Ws[2][16][66];  // [buf][kpair][n],   pad 2
    int tid = threadIdx.x;
    int row0 = blockIdx.x * 64;
    int tx = tid & 7, ty = tid >> 3;   // cols tx*8..+7, rows ty*4..+3

    u64 acc[4][8];
#pragma unroll
    for (int i = 0; i < 4; i++)
#pragma unroll
        for (int j = 0; j < 8; j++) acc[i][j] = 0ull;

    float4 xv[4], wv[4];
    // prefetch tile 0: idx -> row r = idx>>3, float4 q = idx&7 (coalesced)
#pragma unroll
    for (int i = 0; i < 4; i++) {
        int idx = tid + (i << 7);
        int r = idx >> 3, q = idx & 7;
        xv[i] = *(const float4*)(X + (size_t)(row0 + r) * DM + q * 4);
        wv[i] = *(const float4*)(g_Bs + (size_t)r * DM + q * 4);
    }
#pragma unroll
    for (int i = 0; i < 4; i++) {
        int idx = tid + (i << 7);
        int r = idx >> 3, q = idx & 7;
        Xs[0][2 * q][r]     = pack2(xv[i].x, xv[i].y);
        Xs[0][2 * q + 1][r] = pack2(xv[i].z, xv[i].w);
        Ws[0][2 * q][r]     = pack2(wv[i].x, wv[i].y);
        Ws[0][2 * q + 1][r] = pack2(wv[i].z, wv[i].w);
    }
    __syncthreads();

    for (int t = 0; t < 32; t++) {
        int cur = t & 1;
        if (t < 31) {   // prefetch next tile into registers (overlaps compute)
            int k0 = (t + 1) * 32;
#pragma unroll
            for (int i = 0; i < 4; i++) {
                int idx = tid + (i << 7);
                int r = idx >> 3, q = idx & 7;
                xv[i] = *(const float4*)(X + (size_t)(row0 + r) * DM + k0 + q * 4);
                wv[i] = *(const float4*)(g_Bs + (size_t)r * DM + k0 + q * 4);
            }
        }
#pragma unroll
        for (int kp = 0; kp < 16; kp++) {
            ulonglong2 xa = *(const ulonglong2*)&Xs[cur][kp][ty * 4];
            ulonglong2 xb = *(const ulonglong2*)&Xs[cur][kp][ty * 4 + 2];
            ulonglong2 wa = *(const ulonglong2*)&Ws[cur][kp][tx * 8];
            ulonglong2 wb = *(const ulonglong2*)&Ws[cur][kp][tx * 8 + 2];
            ulonglong2 wc = *(const ulonglong2*)&Ws[cur][kp][tx * 8 + 4];
            ulonglong2 wd = *(const ulonglong2*)&Ws[cur][kp][tx * 8 + 6];
            u64 xr[4] = {xa.x, xa.y, xb.x, xb.y};
            u64 wr[8] = {wa.x, wa.y, wb.x, wb.y, wc.x, wc.y, wd.x, wd.y};
#pragma unroll
            for (int i = 0; i < 4; i++)
#pragma unroll
                for (int j = 0; j < 8; j++) acc[i][j] = fma2_(xr[i], wr[j], acc[i][j]);
        }
        if (t < 31) {
            int nb = cur ^ 1;
#pragma unroll
            for (int i = 0; i < 4; i++) {
                int idx = tid + (i << 7);
                int r = idx >> 3, q = idx & 7;
                Xs[nb][2 * q][r]     = pack2(xv[i].x, xv[i].y);
                Xs[nb][2 * q + 1][r] = pack2(xv[i].z, xv[i].w);
                Ws[nb][2 * q][r]     = pack2(wv[i].x, wv[i].y);
                Ws[nb][2 * q + 1][r] = pack2(wv[i].z, wv[i].w);
            }
        }
        __syncthreads();
    }

    // epilogue: lo(even-k)+hi(odd-k), store permuted U, fused row-min
#pragma unroll
    for (int i = 0; i < 4; i++) {
        int row = row0 + ty * 4 + i;
        float rmin = 3.4e38f;
#pragma unroll
        for (int j = 0; j < 8; j++) {
            float lo, hi;
            unpack2(acc[i][j], lo, hi);
            float v = lo + hi;
            g_U[(size_t)row * NS + permn(tx * 8 + j)] = v;
            rmin = fminf(rmin, v);
        }
        rmin = fminf(rmin, __shfl_xor_sync(0xffffffffu, rmin, 1, 8));
        rmin = fminf(rmin, __shfl_xor_sync(0xffffffffu, rmin, 2, 8));
        rmin = fminf(rmin, __shfl_xor_sync(0xffffffffu, rmin, 4, 8));
        if (tx == 0) g_umin[row] = rmin;
    }
}

// ---------------- kernel 3 helpers: full (slow) step ----------------
template <bool WRITE_Y>
__device__ __forceinline__ void slow_step(
    int b, int s, const float* __restrict__ xs, float* __restrict__ ys,
    float* h, int sl, int d, int lp, int dloc) {
    float xv = xs[(sl << 5) + dloc];
    const ulonglong2* up = (const ulonglong2*)(
        g_U + (((size_t)b * SEQ + s) << 6) + (lp << 4));
    ulonglong2 u0 = up[0], u1 = up[1], u2 = up[2], u3 = up[3];
    const ulonglong2* ap = (const ulonglong2*)(
        g_Aperm + ((size_t)d << 6) + (lp << 4));
    ulonglong2 a0 = ap[0], a1 = ap[1], a2 = ap[2], a3 = ap[3];
    u64 xp = pack2(xv, xv);
    step_pair(h[0],  h[1],  u0.x, xp, a0.x);
    step_pair(h[2],  h[3],  u0.y, xp, a0.y);
    step_pair(h[4],  h[5],  u1.x, xp, a1.x);
    step_pair(h[6],  h[7],  u1.y, xp, a1.y);
    step_pair(h[8],  h[9],  u2.x, xp, a2.x);
    step_pair(h[10], h[11], u2.y, xp, a2.y);
    step_pair(h[12], h[13], u3.x, xp, a3.x);
    step_pair(h[14], h[15], u3.y, xp, a3.y);
    if (WRITE_Y) {
        const ulonglong2* cp = (const ulonglong2*)(
            g_Cperm + ((size_t)d << 6) + (lp << 4));
        ulonglong2 c0 = cp[0], c1 = cp[1], c2 = cp[2], c3 = cp[3];
        u64 p2 = 0ull;
        dot_pair(p2, h[0],  h[1],  c0.x);
        dot_pair(p2, h[2],  h[3],  c0.y);
        dot_pair(p2, h[4],  h[5],  c1.x);
        dot_pair(p2, h[6],  h[7],  c1.y);
        dot_pair(p2, h[8],  h[9],  c2.x);
        dot_pair(p2, h[10], h[11], c2.y);
        dot_pair(p2, h[12], h[13], c3.x);
        dot_pair(p2, h[14], h[15], c3.y);
        float plo, phi;
        unpack2(p2, plo, phi);
        float p = plo + phi;
        p += __shfl_xor_sync(0xffffffffu, p, 1, 4);
        p += __shfl_xor_sync(0xffffffffu, p, 2, 4);
        if (lp == 0) ys[(sl << 5) + dloc] = p;
    }
}

// ---------------- kernel 3: chunked scan, mask-staged saturation ----------
// grid (D/32, NCHUNK, B), block 128. Warp owns 8 d's (4 lanes each), lane
// owns 16 n-states. x*umin >= 1 forces ALL states of a d to exactly 1.0
// (RN monotone, h*A >= 0) and y_d = sumC. The saturation test runs in the
// STAGING phase (values already in registers); each (sl, q-group) result
// is one smem byte. After the sync each warp builds its 64-bit mask with
// 2 LDS.64 + 2 ballots, prefilled ys supplies y for saturated steps, and
// the scan loop visits only the ~3% slow bits via __ffs.
__global__ void __launch_bounds__(128, 8) scan_kernel(const float* __restrict__ X,
                                                      float* __restrict__ Hout) {
    __shared__ __align__(16) float xs[SCH * 32];        // x chunk [sl][dloc]
    __shared__ __align__(16) float ys[SCH * 32];        // y chunk (pre-norm)
    __shared__ __align__(8) unsigned char satb[SCH * 8]; // [sl][q] saturation byte

    int b = blockIdx.z;
    int c = blockIdx.y;
    int dbase = blockIdx.x << 5;
    int tid = threadIdx.x;
    int warp = tid >> 5, lane = tid & 31;
    int grp = lane >> 2, lp = lane & 3;
    int dloc = (warp << 3) | grp;    // 0..31
    int d = dbase + dloc;
    int qme = tid & 7;               // staging column group

    float h[16];
    bool ones = false;
#pragma unroll
    for (int j = 0; j < 16; j++) h[j] = 0.0f;
    float4 sumC4 = *(const float4*)(g_sumC + dbase + (qme << 2));

    const size_t xbase = (size_t)b * SEQ * DM;
    const int s_out0 = c * CHUNK;
    const int s_begin = (c == 0) ? 0 : s_out0 - WARM;
    const int s_end = s_out0 + CHUNK;

    for (int s0 = s_begin; s0 < s_end; s0 += SCH) {
        bool writey = (s0 >= s_out0);
        __syncthreads();                       // prev chunk fully consumed
#pragma unroll
        for (int i = 0; i < 4; i++) {          // stage + test (one owner per (sl,q))
            int idx = tid + (i << 7);
            int sl = idx >> 3;
            float4 xv = *(const float4*)(X + xbase + (size_t)(s0 + sl) * DM +
                                         dbase + (qme << 2));
            float um = __ldg(g_umin + (size_t)b * SEQ + s0 + sl);
            bool bb = (xv.x * um >= 1.0f) & (xv.y * um >= 1.0f) &
                      (xv.z * um >= 1.0f) & (xv.w * um >= 1.0f);
            ((float4*)xs)[idx] = xv;
            if (writey) ((float4*)ys)[idx] = sumC4;
            satb[sl * 8 + qme] = bb ? 1 : 0;
        }
        __syncthreads();                       // xs, ys prefill, satb visible

        // build this warp's 64-bit saturation mask: lane l checks sl=l, sl=32+l
        const u64* sp = (const u64*)satb;
        u64 v0 = sp[lane];
        u64 v1 = sp[32 + lane];
        int sh = warp << 4;                    // bytes 2w, 2w+1
        u32 sat0 = __ballot_sync(0xffffffffu, ((v0 >> sh) & 0xFFFFull) == 0x0101ull);
        u32 sat1 = __ballot_sync(0xffffffffu, ((v1 >> sh) & 0xFFFFull) == 0x0101ull);

        u32 w0 = ~sat0, w1 = ~sat1;
        while (w0) {
            int sl = __ffs(w0) - 1;
            w0 &= w0 - 1;
            bool ps = sl ? ((sat0 >> (sl - 1)) & 1u) : ones;
            if (ps) {
#pragma unroll
                for (int j = 0; j < 16; j++) h[j] = 1.0f;
            }
            if (writey) slow_step<true>(b, s0 + sl, xs, ys, h, sl, d, lp, dloc);
            else        slow_step<false>(b, s0 + sl, xs, ys, h, sl, d, lp, dloc);
        }
        while (w1) {
            int t = __ffs(w1) - 1;
            w1 &= w1 - 1;
            int sl = 32 + t;
            bool ps = t ? ((sat1 >> (t - 1)) & 1u) : ((sat0 >> 31) & 1u);
            if (ps) {
#pragma unroll
                for (int j = 0; j < 16; j++) h[j] = 1.0f;
            }
            if (writey) slow_step<true>(b, s0 + sl, xs, ys, h, sl, d, lp, dloc);
            else        slow_step<false>(b, s0 + sl, xs, ys, h, sl, d, lp, dloc);
        }
        ones = ((sat1 >> 31) & 1u) != 0;

        if (writey) {
            __syncthreads();
            // dump y chunk as bf16 (coalesced) into g_Ybf
#pragma unroll
            for (int i = 0; i < 4; i++) {
                int idx = tid + (i << 7);
                int sl = idx >> 3, q = idx & 7;
                float4 v = ((float4*)ys)[idx];
                __nv_bfloat162 p0 = __floats2bfloat162_rn(v.x, v.y);
                __nv_bfloat162 p1 = __floats2bfloat162_rn(v.z, v.w);
                uint2 pk;
                pk.x = *(u32*)&p0;
                pk.y = *(u32*)&p1;
                *(uint2*)(g_Ybf + ((size_t)b * SEQ + s0 + sl) * DM + dbase + (q << 2)) = pk;
            }
        }
    }

    if (Hout && c == NCHUNK - 1) {   // h_final [B, D, N], lane lp owns n = lp + 4j
#pragma unroll
        for (int j = 0; j < 16; j++) {
            float hv = ones ? 1.0f : h[j];
            Hout[(((size_t)b * DM + d) << 6) + lp + (j << 2)] = hv;
        }
    }
}

// ---------------- kernel 4: normalize + residual + clip ----------------
__global__ void __launch_bounds__(256) finalize_kernel(const float* __restrict__ X,
                                                       float* __restrict__ out) {
    size_t row = blockIdx.x;   // b*SEQ + s
    int tid = threadIdx.x;
    uint2 yv = *(const uint2*)(g_Ybf + row * DM + tid * 4);
    __nv_bfloat162 y0 = *(__nv_bfloat162*)&yv.x;
    __nv_bfloat162 y1 = *(__nv_bfloat162*)&yv.y;
    float2 f0 = __bfloat1622float2(y0);
    float2 f1 = __bfloat1622float2(y1);
    float4 v = make_float4(f0.x, f0.y, f1.x, f1.y);
    float ps = v.x + v.y + v.z + v.w;
#pragma unroll
    for (int o = 16; o; o >>= 1) ps += __shfl_xor_sync(0xffffffffu, ps, o);
    __shared__ float wsum[8];
    if ((tid & 31) == 0) wsum[tid >> 5] = ps;
    __syncthreads();
    float tot = 0.0f;
#pragma unroll
    for (int w = 0; w < 8; w++) tot += wsum[w];
    float inv = 1.0f / (tot + 1e-6f);
    float4 xv = ((const float4*)(X + row * DM))[tid];
    float4 gv = ((const float4*)g_g)[tid];
    float4 r;
    r.x = __saturatef(fmaf(v.x * gv.x, inv, xv.x));
    r.y = __saturatef(fmaf(v.y * gv.y, inv, xv.y));
    r.z = __saturatef(fmaf(v.z * gv.z, inv, xv.z));
    r.w = __saturatef(fmaf(v.w * gv.w, inv, xv.w));
    ((float4*)(out + row * DM))[tid] = r;
}

// ---------------- launch ----------------
extern "C" void kernel_launch(void* const* d_in, const int* in_sizes, int n_in,
                              void* d_out, int out_size) {
    const float* x     = (const float*)d_in[0];
    const float* A_raw = (const float*)d_in[1];
    const float* B_w   = (const float*)d_in[2];
    const float* C_w   = (const float*)d_in[3];
    const float* gamma = (const float*)d_in[4];
    float* out = (float*)d_out;

    const size_t Y_ELEMS = (size_t)BB * SEQ * DM;       // 33,554,432
    const size_t H_ELEMS = (size_t)BB * DM * NS;        // 524,288
    float* hout = ((size_t)out_size >= Y_ELEMS + H_ELEMS) ? (out + Y_ELEMS) : nullptr;

    prep_kernel<<<256, 256>>>(A_raw, B_w, C_w, gamma);
    gemm_kernel<<<(BB * SEQ) / 64, 128>>>(x);
    scan_kernel<<<dim3(DM / 32, NCHUNK, BB), 128>>>(x, hout);
    finalize_kernel<<<BB * SEQ, 256>>>(x, out);
}

// round 17
// speedup vs baseline: 1.5079x; 1.5079x over previous
#include <cuda_runtime.h>
#include <cuda_bf16.h>
#include <math.h>

#define BB 8
#define SEQ 4096
#define DM 1024
#define NS 64
#define SCH 64          // scan steps per smem chunk
#define CHUNK 512       // sequence chunk per CTA (parallel-in-time)
#define WARM 64         // warmup steps (state error <= 0.7311^64 ~ 2e-9)
#define NCHUNK (SEQ / CHUNK)

typedef unsigned long long u64;
typedef unsigned int u32;

// ---------------- static scratch (no allocations allowed) ----------------
__device__ __align__(16) float g_Bs[NS * DM];              // sigmoid(B_w), [N, D]
__device__ __align__(16) float g_Aperm[DM * NS];           // sigmoid(A_raw), permuted n
__device__ __align__(16) float g_Cperm[DM * NS];           // sigmoid(C_w), permuted n
__device__ __align__(16) float g_g[DM];                    // sigmoid(gamma)
__device__ __align__(16) float g_sumC[DM];                 // sum_n sigmoid(C_w[d,n])
__device__ __align__(16) float g_U[(size_t)BB * SEQ * NS]; // X @ Bm^T, permuted n
__device__ __align__(16) float g_umin[(size_t)BB * SEQ];   // min_n U[b,s,n]
__device__ __align__(16) __nv_bfloat16 g_Ybf[(size_t)BB * SEQ * DM]; // y pre-norm, bf16

__device__ __forceinline__ float sigmoidf_(float v) {
    return 1.0f / (1.0f + expf(-v));
}

// ---------------- packed f32x2 helpers ----------------
__device__ __forceinline__ u64 pack2(float lo, float hi) {
    u64 r;
    asm("mov.b64 %0, {%1, %2};" : "=l"(r) : "f"(lo), "f"(hi));
    return r;
}
__device__ __forceinline__ void unpack2(u64 v, float& lo, float& hi) {
    asm("mov.b64 {%0, %1}, %2;" : "=f"(lo), "=f"(hi) : "l"(v));
}
__device__ __forceinline__ u64 fma2_(u64 a, u64 b, u64 c) {
    u64 r;
    asm("fma.rn.f32x2 %0, %1, %2, %3;" : "=l"(r) : "l"(a), "l"(b), "l"(c));
    return r;
}

// State update, one pair: h = min(1, h*A + u*x). Lower clip provably dead
// (u>=0, x>=0, A>0, h0=0 => h*A+u*x >= 0). min on ALU pipe.
__device__ __forceinline__ void step_pair(float& h0, float& h1, u64 u2, u64 xp, u64 a2) {
    asm("{\n\t"
        ".reg .b64 t, hp;\n\t"
        "mul.rn.f32x2 t, %2, %3;\n\t"
        "mov.b64 hp, {%0, %1};\n\t"
        "fma.rn.f32x2 hp, hp, %4, t;\n\t"
        "mov.b64 {%0, %1}, hp;\n\t"
        "}\n\t"
        : "+f"(h0), "+f"(h1) : "l"(u2), "l"(xp), "l"(a2));
    h0 = fminf(h0, 1.0f);
    h1 = fminf(h1, 1.0f);
}

__device__ __forceinline__ void dot_pair(u64& p2, float h0, float h1, u64 c2) {
    asm("{\n\t"
        ".reg .b64 hp;\n\t"
        "mov.b64 hp, {%1, %2};\n\t"
        "fma.rn.f32x2 %0, hp, %3, %0;\n\t"
        "}\n\t"
        : "+l"(p2) : "f"(h0), "f"(h1), "l"(c2));
}

// permutation: state n -> storage position, lane lp=n%4 owns n = lp + 4j,
// stored at lp*16 + j so each lane reads 16 contiguous floats (4x LDG.128)
__device__ __forceinline__ int permn(int n) { return ((n & 3) << 4) | (n >> 2); }

// ---------------- kernel 1: precompute sigmoids ----------------
__global__ void prep_kernel(const float* __restrict__ A_raw,
                            const float* __restrict__ B_w,
                            const float* __restrict__ C_w,
                            const float* __restrict__ gamma) {
    int i = blockIdx.x * 256 + threadIdx.x;
    if (i < NS * DM) {
        g_Bs[i] = sigmoidf_(B_w[i]);           // B_w is [N, D]
        int d = i >> 6, n = i & 63;            // A_raw / C_w are [D, N]
        int p = permn(n);
        g_Aperm[(d << 6) + p] = sigmoidf_(A_raw[i]);
        g_Cperm[(d << 6) + p] = sigmoidf_(C_w[i]);
    }
    if (i < DM) {
        g_g[i] = sigmoidf_(gamma[i]);
        float s = 0.0f;
        for (int n = 0; n < NS; n++) s += sigmoidf_(C_w[i * NS + n]);
        g_sumC[i] = s;    // y_d when all 64 states saturate at 1.0
    }
}

// ---------------- kernel 2: U = X @ Bs^T, double-buffered + fused umin ----
// 64 rows x 64 cols per block, 256 threads, thread = 4 rows x 4 cols via
// f32x2 (x duplicated by pack, w consumed as natural pairs from smem).
// Two smem buffers: prefetch tile t+1 into registers while computing t.
// umin fused in the epilogue: row-min over 4 local cols + 16 tx lanes.
__global__ void __launch_bounds__(256) gemm_kernel(const float* __restrict__ X) {
    __shared__ __align__(16) float Xs[2][32][68];  // k-major, padded
    __shared__ __align__(16) float Ws[2][32][68];
    int tid = threadIdx.x;
    int row0 = blockIdx.x * 64;
    int tx = tid & 15, ty = tid >> 4;
    int r0 = tid >> 3, r1 = r0 + 32, q = tid & 7;  // staging coords
    u64 acc2[4][2];
#pragma unroll
    for (int i = 0; i < 4; i++) { acc2[i][0] = 0ull; acc2[i][1] = 0ull; }

    float4 xv0, xv1, wv0, wv1;
    xv0 = *(const float4*)(X + (size_t)(row0 + r0) * DM + q * 4);
    xv1 = *(const float4*)(X + (size_t)(row0 + r1) * DM + q * 4);
    wv0 = *(const float4*)(g_Bs + (size_t)r0 * DM + q * 4);
    wv1 = *(const float4*)(g_Bs + (size_t)r1 * DM + q * 4);
    Xs[0][q * 4 + 0][r0] = xv0.x; Xs[0][q * 4 + 1][r0] = xv0.y;
    Xs[0][q * 4 + 2][r0] = xv0.z; Xs[0][q * 4 + 3][r0] = xv0.w;
    Xs[0][q * 4 + 0][r1] = xv1.x; Xs[0][q * 4 + 1][r1] = xv1.y;
    Xs[0][q * 4 + 2][r1] = xv1.z; Xs[0][q * 4 + 3][r1] = xv1.w;
    Ws[0][q * 4 + 0][r0] = wv0.x; Ws[0][q * 4 + 1][r0] = wv0.y;
    Ws[0][q * 4 + 2][r0] = wv0.z; Ws[0][q * 4 + 3][r0] = wv0.w;
    Ws[0][q * 4 + 0][r1] = wv1.x; Ws[0][q * 4 + 1][r1] = wv1.y;
    Ws[0][q * 4 + 2][r1] = wv1.z; Ws[0][q * 4 + 3][r1] = wv1.w;
    __syncthreads();

    for (int t = 0; t < 32; t++) {
        int cur = t & 1;
        if (t < 31) {   // prefetch next tile into registers (overlaps compute)
            int k0 = (t + 1) * 32;
            xv0 = *(const float4*)(X + (size_t)(row0 + r0) * DM + k0 + q * 4);
            xv1 = *(const float4*)(X + (size_t)(row0 + r1) * DM + k0 + q * 4);
            wv0 = *(const float4*)(g_Bs + (size_t)r0 * DM + k0 + q * 4);
            wv1 = *(const float4*)(g_Bs + (size_t)r1 * DM + k0 + q * 4);
        }
#pragma unroll
        for (int k = 0; k < 32; k++) {
            float4 xa = *(const float4*)&Xs[cur][k][ty * 4];
            ulonglong2 wv = *(const ulonglong2*)&Ws[cur][k][tx * 4];
            u64 xp[4] = {pack2(xa.x, xa.x), pack2(xa.y, xa.y),
                         pack2(xa.z, xa.z), pack2(xa.w, xa.w)};
#pragma unroll
            for (int i = 0; i < 4; i++) {
                acc2[i][0] = fma2_(xp[i], wv.x, acc2[i][0]);
                acc2[i][1] = fma2_(xp[i], wv.y, acc2[i][1]);
            }
        }
        if (t < 31) {
            int nb = cur ^ 1;
            Xs[nb][q * 4 + 0][r0] = xv0.x; Xs[nb][q * 4 + 1][r0] = xv0.y;
            Xs[nb][q * 4 + 2][r0] = xv0.z; Xs[nb][q * 4 + 3][r0] = xv0.w;
            Xs[nb][q * 4 + 0][r1] = xv1.x; Xs[nb][q * 4 + 1][r1] = xv1.y;
            Xs[nb][q * 4 + 2][r1] = xv1.z; Xs[nb][q * 4 + 3][r1] = xv1.w;
            Ws[nb][q * 4 + 0][r0] = wv0.x; Ws[nb][q * 4 + 1][r0] = wv0.y;
            Ws[nb][q * 4 + 2][r0] = wv0.z; Ws[nb][q * 4 + 3][r0] = wv0.w;
            Ws[nb][q * 4 + 0][r1] = wv1.x; Ws[nb][q * 4 + 1][r1] = wv1.y;
            Ws[nb][q * 4 + 2][r1] = wv1.z; Ws[nb][q * 4 + 3][r1] = wv1.w;
        }
        __syncthreads();
    }

    // epilogue: store permuted U + fused row-min (width-16 shfl over tx)
#pragma unroll
    for (int i = 0; i < 4; i++) {
        float a0, a1, a2, a3;
        unpack2(acc2[i][0], a0, a1);
        unpack2(acc2[i][1], a2, a3);
        int row = row0 + ty * 4 + i;
        size_t rb = (size_t)row * NS;
        g_U[rb + permn(tx * 4 + 0)] = a0;
        g_U[rb + permn(tx * 4 + 1)] = a1;
        g_U[rb + permn(tx * 4 + 2)] = a2;
        g_U[rb + permn(tx * 4 + 3)] = a3;
        float rmin = fminf(fminf(a0, a1), fminf(a2, a3));
        rmin = fminf(rmin, __shfl_xor_sync(0xffffffffu, rmin, 1, 16));
        rmin = fminf(rmin, __shfl_xor_sync(0xffffffffu, rmin, 2, 16));
        rmin = fminf(rmin, __shfl_xor_sync(0xffffffffu, rmin, 4, 16));
        rmin = fminf(rmin, __shfl_xor_sync(0xffffffffu, rmin, 8, 16));
        if (tx == 0) g_umin[row] = rmin;
    }
}

// ---------------- kernel 3 helpers: full (slow) step ----------------
template <bool WRITE_Y>
__device__ __forceinline__ void slow_step(
    int b, int s, const float* __restrict__ xs, float* __restrict__ ys,
    float* h, int sl, int d, int lp, int dloc) {
    float xv = xs[(sl << 5) + dloc];
    const ulonglong2* up = (const ulonglong2*)(
        g_U + (((size_t)b * SEQ + s) << 6) + (lp << 4));
    ulonglong2 u0 = up[0], u1 = up[1], u2 = up[2], u3 = up[3];
    const ulonglong2* ap = (const ulonglong2*)(
        g_Aperm + ((size_t)d << 6) + (lp << 4));
    ulonglong2 a0 = ap[0], a1 = ap[1], a2 = ap[2], a3 = ap[3];
    u64 xp = pack2(xv, xv);
    step_pair(h[0],  h[1],  u0.x, xp, a0.x);
    step_pair(h[2],  h[3],  u0.y, xp, a0.y);
    step_pair(h[4],  h[5],  u1.x, xp, a1.x);
    step_pair(h[6],  h[7],  u1.y, xp, a1.y);
    step_pair(h[8],  h[9],  u2.x, xp, a2.x);
    step_pair(h[10], h[11], u2.y, xp, a2.y);
    step_pair(h[12], h[13], u3.x, xp, a3.x);
    step_pair(h[14], h[15], u3.y, xp, a3.y);
    if (WRITE_Y) {
        const ulonglong2* cp = (const ulonglong2*)(
            g_Cperm + ((size_t)d << 6) + (lp << 4));
        ulonglong2 c0 = cp[0], c1 = cp[1], c2 = cp[2], c3 = cp[3];
        u64 p2 = 0ull;
        dot_pair(p2, h[0],  h[1],  c0.x);
        dot_pair(p2, h[2],  h[3],  c0.y);
        dot_pair(p2, h[4],  h[5],  c1.x);
        dot_pair(p2, h[6],  h[7],  c1.y);
        dot_pair(p2, h[8],  h[9],  c2.x);
        dot_pair(p2, h[10], h[11], c2.y);
        dot_pair(p2, h[12], h[13], c3.x);
        dot_pair(p2, h[14], h[15], c3.y);
        float plo, phi;
        unpack2(p2, plo, phi);
        float p = plo + phi;
        p += __shfl_xor_sync(0xffffffffu, p, 1, 4);
        p += __shfl_xor_sync(0xffffffffu, p, 2, 4);
        if (lp == 0) ys[(sl << 5) + dloc] = p;
    }
}

// ---------------- kernel 3: chunked scan, mask-staged saturation ----------
// grid (D/32, NCHUNK, B), block 128. Warp owns 8 d's (4 lanes each), lane
// owns 16 n-states. x*umin >= 1 forces ALL states of a d to exactly 1.0
// (RN monotone, h*A >= 0) and y_d = sumC. The saturation test runs in the
// STAGING phase (values already in registers); each (sl, q-group) result
// is one smem byte. After the sync each warp builds its 64-bit mask with
// 2 LDS.64 + 2 ballots, prefilled ys supplies y for saturated steps, and
// the scan loop visits only the ~3% slow bits via __ffs.
__global__ void __launch_bounds__(128, 8) scan_kernel(const float* __restrict__ X,
                                                      float* __restrict__ Hout) {
    __shared__ __align__(16) float xs[SCH * 32];        // x chunk [sl][dloc]
    __shared__ __align__(16) float ys[SCH * 32];        // y chunk (pre-norm)
    __shared__ __align__(8) unsigned char satb[SCH * 8]; // [sl][q] saturation byte

    int b = blockIdx.z;
    int c = blockIdx.y;
    int dbase = blockIdx.x << 5;
    int tid = threadIdx.x;
    int warp = tid >> 5, lane = tid & 31;
    int grp = lane >> 2, lp = lane & 3;
    int dloc = (warp << 3) | grp;    // 0..31
    int d = dbase + dloc;
    int qme = tid & 7;               // staging column group

    float h[16];
    bool ones = false;
#pragma unroll
    for (int j = 0; j < 16; j++) h[j] = 0.0f;
    float4 sumC4 = *(const float4*)(g_sumC + dbase + (qme << 2));

    const size_t xbase = (size_t)b * SEQ * DM;
    const int s_out0 = c * CHUNK;
    const int s_begin = (c == 0) ? 0 : s_out0 - WARM;
    const int s_end = s_out0 + CHUNK;

    for (int s0 = s_begin; s0 < s_end; s0 += SCH) {
        bool writey = (s0 >= s_out0);
        __syncthreads();                       // prev chunk fully consumed
#pragma unroll
        for (int i = 0; i < 4; i++) {          // stage + test (one owner per (sl,q))
            int idx = tid + (i << 7);
            int sl = idx >> 3;
            float4 xv = *(const float4*)(X + xbase + (size_t)(s0 + sl) * DM +
                                         dbase + (qme << 2));
            float um = __ldg(g_umin + (size_t)b * SEQ + s0 + sl);
            bool bb = (xv.x * um >= 1.0f) & (xv.y * um >= 1.0f) &
                      (xv.z * um >= 1.0f) & (xv.w * um >= 1.0f);
            ((float4*)xs)[idx] = xv;
            if (writey) ((float4*)ys)[idx] = sumC4;
            satb[sl * 8 + qme] = bb ? 1 : 0;
        }
        __syncthreads();                       // xs, ys prefill, satb visible

        // build this warp's 64-bit saturation mask: lane l checks sl=l, sl=32+l
        const u64* sp = (const u64*)satb;
        u64 v0 = sp[lane];
        u64 v1 = sp[32 + lane];
        int sh = warp << 4;                    // bytes 2w, 2w+1
        u32 sat0 = __ballot_sync(0xffffffffu, ((v0 >> sh) & 0xFFFFull) == 0x0101ull);
        u32 sat1 = __ballot_sync(0xffffffffu, ((v1 >> sh) & 0xFFFFull) == 0x0101ull);

        u32 w0 = ~sat0, w1 = ~sat1;
        while (w0) {
            int sl = __ffs(w0) - 1;
            w0 &= w0 - 1;
            bool ps = sl ? ((sat0 >> (sl - 1)) & 1u) : ones;
            if (ps) {
#pragma unroll
                for (int j = 0; j < 16; j++) h[j] = 1.0f;
            }
            if (writey) slow_step<true>(b, s0 + sl, xs, ys, h, sl, d, lp, dloc);
            else        slow_step<false>(b, s0 + sl, xs, ys, h, sl, d, lp, dloc);
        }
        while (w1) {
            int t = __ffs(w1) - 1;
            w1 &= w1 - 1;
            int sl = 32 + t;
            bool ps = t ? ((sat1 >> (t - 1)) & 1u) : ((sat0 >> 31) & 1u);
            if (ps) {
#pragma unroll
                for (int j = 0; j < 16; j++) h[j] = 1.0f;
            }
            if (writey) slow_step<true>(b, s0 + sl, xs, ys, h, sl, d, lp, dloc);
            else        slow_step<false>(b, s0 + sl, xs, ys, h, sl, d, lp, dloc);
        }
        ones = ((sat1 >> 31) & 1u) != 0;

        if (writey) {
            __syncthreads();
            // dump y chunk as bf16 (coalesced) into g_Ybf
#pragma unroll
            for (int i = 0; i < 4; i++) {
                int idx = tid + (i << 7);
                int sl = idx >> 3, q = idx & 7;
                float4 v = ((float4*)ys)[idx];
                __nv_bfloat162 p0 = __floats2bfloat162_rn(v.x, v.y);
                __nv_bfloat162 p1 = __floats2bfloat162_rn(v.z, v.w);
                uint2 pk;
                pk.x = *(u32*)&p0;
                pk.y = *(u32*)&p1;
                *(uint2*)(g_Ybf + ((size_t)b * SEQ + s0 + sl) * DM + dbase + (q << 2)) = pk;
            }
        }
    }

    if (Hout && c == NCHUNK - 1) {   // h_final [B, D, N], lane lp owns n = lp + 4j
#pragma unroll
        for (int j = 0; j < 16; j++) {
            float hv = ones ? 1.0f : h[j];
            Hout[(((size_t)b * DM + d) << 6) + lp + (j << 2)] = hv;
        }
    }
}

// ---------------- kernel 4: normalize + residual + clip ----------------
__global__ void __launch_bounds__(256) finalize_kernel(const float* __restrict__ X,
                                                       float* __restrict__ out) {
    size_t row = blockIdx.x;   // b*SEQ + s
    int tid = threadIdx.x;
    uint2 yv = *(const uint2*)(g_Ybf + row * DM + tid * 4);
    __nv_bfloat162 y0 = *(__nv_bfloat162*)&yv.x;
    __nv_bfloat162 y1 = *(__nv_bfloat162*)&yv.y;
    float2 f0 = __bfloat1622float2(y0);
    float2 f1 = __bfloat1622float2(y1);
    float4 v = make_float4(f0.x, f0.y, f1.x, f1.y);
    float ps = v.x + v.y + v.z + v.w;
#pragma unroll
    for (int o = 16; o; o >>= 1) ps += __shfl_xor_sync(0xffffffffu, ps, o);
    __shared__ float wsum[8];
    if ((tid & 31) == 0) wsum[tid >> 5] = ps;
    __syncthreads();
    float tot = 0.0f;
#pragma unroll
    for (int w = 0; w < 8; w++) tot += wsum[w];
    float inv = 1.0f / (tot + 1e-6f);
    float4 xv = ((const float4*)(X + row * DM))[tid];
    float4 gv = ((const float4*)g_g)[tid];
    float4 r;
    r.x = __saturatef(fmaf(v.x * gv.x, inv, xv.x));
    r.y = __saturatef(fmaf(v.y * gv.y, inv, xv.y));
    r.z = __saturatef(fmaf(v.z * gv.z, inv, xv.z));
    r.w = __saturatef(fmaf(v.w * gv.w, inv, xv.w));
    ((float4*)(out + row * DM))[tid] = r;
}

// ---------------- launch ----------------
extern "C" void kernel_launch(void* const* d_in, const int* in_sizes, int n_in,
                              void* d_out, int out_size) {
    const float* x     = (const float*)d_in[0];
    const float* A_raw = (const float*)d_in[1];
    const float* B_w   = (const float*)d_in[2];
    const float* C_w   = (const float*)d_in[3];
    const float* gamma = (const float*)d_in[4];
    float* out = (float*)d_out;

    const size_t Y_ELEMS = (size_t)BB * SEQ * DM;       // 33,554,432
    const size_t H_ELEMS = (size_t)BB * DM * NS;        // 524,288
    float* hout = ((size_t)out_size >= Y_ELEMS + H_ELEMS) ? (out + Y_ELEMS) : nullptr;

    prep_kernel<<<256, 256>>>(A_raw, B_w, C_w, gamma);
    gemm_kernel<<<(BB * SEQ) / 64, 256>>>(x);
    scan_kernel<<<dim3(DM / 32, NCHUNK, BB), 128>>>(x, hout);
    finalize_kernel<<<BB * SEQ, 256>>>(x, out);
}